// round 3
// baseline (speedup 1.0000x reference)
#include <cuda_runtime.h>
#include <math.h>

// ---------------------------------------------------------------------------
//   gwc_feature (4,96,160,288)  concat_feature (4,12,160,288)
//   downsample: conv3x3 s2 p1 -> BN -> leaky(0.1) -> conv1x1 -> softmax(9)
//               -> weighted unfold sum   (HO=80, WO=144)
//   volume: D=24, gwc groups=8 (cpg=12), out (2, 32, 24, 80, 144) f32
// ---------------------------------------------------------------------------

#define HO_ 80
#define WO_ 144
#define HW_ (HO_*WO_)

typedef unsigned long long ull;

// scratch (bss, no allocation)
static __device__ float g_y1   [4*192*HW_];
static __device__ float g_mask [4*144*HW_];
static __device__ float g_g8x  [4* 96*HW_];
static __device__ float g_cy1  [4* 24*HW_];
static __device__ float g_cmask[4*108*HW_];
static __device__ float g_c8x  [4* 12*HW_];

__device__ __forceinline__ ull pack2(float lo, float hi) {
    ull r; asm("mov.b64 %0,{%1,%2};" : "=l"(r) : "f"(lo), "f"(hi)); return r;
}
__device__ __forceinline__ void unpack2(ull v, float& lo, float& hi) {
    asm("mov.b64 {%0,%1},%2;" : "=f"(lo), "=f"(hi) : "l"(v));
}
__device__ __forceinline__ void fma2(ull& d, ull a, ull b) {
    asm("fma.rn.f32x2 %0, %1, %2, %0;" : "+l"(d) : "l"(a), "l"(b));
}

// ---------------------------------------------------------------------------
// Implicit-im2col fp32 GEMM using packed f32x2 FMA.
// Tile: 64(oc) x 128(pos), BK=16, 256 threads, 4x8 microtile.
// Register double-buffered global loads. Npos must be a multiple of 128 and
// HW a multiple of 128 (holds: 46080, 11520).
// ---------------------------------------------------------------------------
template<int KS, bool DO_BN>
__global__ void __launch_bounds__(256)
conv_gemm_kernel(
    const float* __restrict__ x, const float* __restrict__ w,
    const float* __restrict__ bn_g, const float* __restrict__ bn_b,
    const float* __restrict__ bn_m, const float* __restrict__ bn_v,
    float* __restrict__ out,
    int Cin, int Cout, int Hin, int Win, int Hout, int Wout,
    int stride, int pad)
{
    __shared__ ull   As2[2][16][65];   // pre-broadcast {a,a} pairs, [k][oc]
    __shared__ float Bs [2][16][128];  // [k][pos]

    const int K  = Cin * KS * KS;
    const int HW = Hout * Wout;

    const int bm = blockIdx.y * 64;
    const int bn = blockIdx.x * 128;
    const int tid = threadIdx.x;

    // ---- loader thread mapping ----
    const int akk = tid & 15;          // A: k within tile
    const int aoc = tid >> 4;          // A: oc base (strides of 16, 4 loads)
    const int bcol = tid & 127;        // B: pos column
    const int bkb  = tid >> 7;         // B: k base (0/1, strides of 2, 8 loads)

    const int posB = bn + bcol;
    const int bbB  = posB / HW;
    const int rpB  = posB - bbB * HW;
    const int hoB  = rpB / Wout;
    const int woB  = rpB - hoB * Wout;

    // ---- compute thread mapping ----
    const int txp = (tid & 15) * 8;    // pos offset (8 wide)
    const int ty  = tid >> 4;          // oc group (4 wide)

    const int nk = (K + 15) >> 4;

    float awR[4];
    float bxR[8];

    // prologue: load tile 0
    #pragma unroll
    for (int i = 0; i < 4; i++) {
        const int oc = bm + aoc + i * 16;
        awR[i] = (oc < Cout && akk < K) ? __ldg(&w[oc * K + akk]) : 0.f;
    }
    #pragma unroll
    for (int i = 0; i < 8; i++) {
        const int k = bkb + 2 * i;
        float v = 0.f;
        if (k < K) {
            int ic, kh, kw2;
            if (KS == 1) { ic = k; kh = 0; kw2 = 0; }
            else { ic = k / 9; int r = k - ic * 9; kh = r / 3; kw2 = r - kh * 3; }
            const int hi = hoB * stride + kh - pad;
            const int wi = woB * stride + kw2 - pad;
            if (hi >= 0 && hi < Hin && wi >= 0 && wi < Win)
                v = __ldg(&x[((size_t)(bbB * Cin + ic) * Hin + hi) * Win + wi]);
        }
        bxR[i] = v;
    }
    #pragma unroll
    for (int i = 0; i < 4; i++) As2[0][akk][aoc + i * 16] = pack2(awR[i], awR[i]);
    #pragma unroll
    for (int i = 0; i < 8; i++) Bs[0][bkb + 2 * i][bcol] = bxR[i];
    __syncthreads();

    ull acc[4][4];
    #pragma unroll
    for (int i = 0; i < 4; i++)
        #pragma unroll
        for (int j = 0; j < 4; j++) acc[i][j] = 0ull;

    for (int t = 0; t < nk; t++) {
        const int cur = t & 1, nxt = cur ^ 1;
        const int k0n = (t + 1) << 4;

        // issue loads for next tile (results consumed after compute)
        if (t + 1 < nk) {
            #pragma unroll
            for (int i = 0; i < 4; i++) {
                const int oc = bm + aoc + i * 16;
                const int ka = k0n + akk;
                awR[i] = (oc < Cout && ka < K) ? __ldg(&w[oc * K + ka]) : 0.f;
            }
            #pragma unroll
            for (int i = 0; i < 8; i++) {
                const int k = k0n + bkb + 2 * i;
                float v = 0.f;
                if (k < K) {
                    int ic, kh, kw2;
                    if (KS == 1) { ic = k; kh = 0; kw2 = 0; }
                    else { ic = k / 9; int r = k - ic * 9; kh = r / 3; kw2 = r - kh * 3; }
                    const int hi = hoB * stride + kh - pad;
                    const int wi = woB * stride + kw2 - pad;
                    if (hi >= 0 && hi < Hin && wi >= 0 && wi < Win)
                        v = __ldg(&x[((size_t)(bbB * Cin + ic) * Hin + hi) * Win + wi]);
                }
                bxR[i] = v;
            }
        }

        // compute over current buffer
        #pragma unroll
        for (int kk = 0; kk < 16; kk++) {
            ull a0 = As2[cur][kk][ty * 4 + 0];
            ull a1 = As2[cur][kk][ty * 4 + 1];
            ull a2 = As2[cur][kk][ty * 4 + 2];
            ull a3 = As2[cur][kk][ty * 4 + 3];
            const ull* bp = reinterpret_cast<const ull*>(&Bs[cur][kk][txp]);
            ull c0 = bp[0], c1 = bp[1], c2 = bp[2], c3 = bp[3];
            fma2(acc[0][0], a0, c0); fma2(acc[0][1], a0, c1);
            fma2(acc[0][2], a0, c2); fma2(acc[0][3], a0, c3);
            fma2(acc[1][0], a1, c0); fma2(acc[1][1], a1, c1);
            fma2(acc[1][2], a1, c2); fma2(acc[1][3], a1, c3);
            fma2(acc[2][0], a2, c0); fma2(acc[2][1], a2, c1);
            fma2(acc[2][2], a2, c2); fma2(acc[2][3], a2, c3);
            fma2(acc[3][0], a3, c0); fma2(acc[3][1], a3, c1);
            fma2(acc[3][2], a3, c2); fma2(acc[3][3], a3, c3);
        }

        if (t + 1 < nk) {
            __syncthreads();   // everyone done reading 'nxt' from 2 iters ago
            #pragma unroll
            for (int i = 0; i < 4; i++) As2[nxt][akk][aoc + i * 16] = pack2(awR[i], awR[i]);
            #pragma unroll
            for (int i = 0; i < 8; i++) Bs[nxt][bkb + 2 * i][bcol] = bxR[i];
            __syncthreads();
        }
    }

    // epilogue: all 128 pos in this tile share one batch index
    const int posb0 = bn + txp;
    const int bb = posb0 / HW;
    const int rp0 = posb0 - bb * HW;

    #pragma unroll
    for (int i = 0; i < 4; i++) {
        const int oc = bm + ty * 4 + i;
        if (oc >= Cout) continue;
        float scale = 1.f, bias = 0.f;
        if (DO_BN) {
            const float s = bn_g[oc] * rsqrtf(bn_v[oc] + 1e-5f);
            scale = s;
            bias  = bn_b[oc] - bn_m[oc] * s;
        }
        float* orow = out + (size_t)(bb * Cout + oc) * HW + rp0;
        #pragma unroll
        for (int j = 0; j < 4; j++) {
            float v0, v1;
            unpack2(acc[i][j], v0, v1);
            if (DO_BN) {
                v0 = v0 * scale + bias;  v0 = (v0 >= 0.f) ? v0 : 0.1f * v0;
                v1 = v1 * scale + bias;  v1 = (v1 >= 0.f) ? v1 : 0.1f * v1;
            }
            float2 vv; vv.x = v0; vv.y = v1;
            *reinterpret_cast<float2*>(&orow[2 * j]) = vv;
        }
    }
}

// ---------------------------------------------------------------------------
// Fused: softmax over 9 logits per (b, group, ho, wo), then weighted unfold
// sum over the 3x3 stride-2 patch. Channel for (i, g) is ch = i*G + g.
// ---------------------------------------------------------------------------
__global__ void adaptive_ds_kernel(
    const float* __restrict__ x, const float* __restrict__ logits,
    float* __restrict__ out,
    int Cin, int G, int Hin, int Win, int Bsz)
{
    const int idx = blockIdx.x * blockDim.x + threadIdx.x;
    const int total = Bsz * G * HW_;
    if (idx >= total) return;

    const int wo = idx % WO_;
    int t = idx / WO_;
    const int ho = t % HO_;  t /= HO_;
    const int g  = t % G;
    const int b  = t / G;

    float lg[9];
    float mx = -1e30f;
    const size_t lbase = ((size_t)(b * G * 9 + g * 9) * HW_) + ho * WO_ + wo;
    #pragma unroll
    for (int k = 0; k < 9; k++) {
        lg[k] = logits[lbase + (size_t)k * HW_];
        mx = fmaxf(mx, lg[k]);
    }
    float s = 0.f;
    #pragma unroll
    for (int k = 0; k < 9; k++) { lg[k] = __expf(lg[k] - mx); s += lg[k]; }
    const float inv = 1.f / s;
    #pragma unroll
    for (int k = 0; k < 9; k++) lg[k] *= inv;

    const int cpg = Cin / G;
    for (int i = 0; i < cpg; i++) {
        const int ch = i * G + g;
        const float* xb = x + (size_t)(b * Cin + ch) * Hin * Win;
        float acc = 0.f;
        #pragma unroll
        for (int kh = 0; kh < 3; kh++) {
            const int hi = 2 * ho + kh - 1;
            if (hi < 0 || hi >= Hin) continue;
            #pragma unroll
            for (int kw = 0; kw < 3; kw++) {
                const int wi = 2 * wo + kw - 1;
                if (wi < 0 || wi >= Win) continue;
                acc += lg[kh * 3 + kw] * __ldg(&xb[(size_t)hi * Win + wi]);
            }
        }
        out[((size_t)(b * Cin + ch) * HW_) + ho * WO_ + wo] = acc;
    }
}

// ---------------------------------------------------------------------------
// Cost volumes. Output (2, 32, 24, 80, 144):
//   c in [0,8):   gwc corr  mean_{cc<12} l[g*12+cc][w] * r[g*12+cc][w-d]
//   c in [8,20):  l_c[c-8][w]       if w>=d else 0
//   c in [20,32): r_c[c-20][w-d]    if w>=d else 0
// ---------------------------------------------------------------------------
__global__ void build_volume_kernel(
    const float* __restrict__ g8x, const float* __restrict__ c8x,
    float* __restrict__ out)
{
    const int W = WO_, H = HO_, D = 24, OC = 32;
    const int total = 2 * OC * D * H * W;
    const int idx = blockIdx.x * blockDim.x + threadIdx.x;
    if (idx >= total) return;

    const int w = idx % W;
    int t = idx / W;
    const int h = t % H;  t /= H;
    const int d = t % D;  t /= D;
    const int c = t % OC;
    const int b = t / OC;

    float v = 0.f;
    if (c < 8) {
        if (w >= d) {
            const float* l = g8x + ((size_t)(b       * 96 + c * 12) * H + h) * W;
            const float* r = g8x + ((size_t)((b + 2) * 96 + c * 12) * H + h) * W;
            float acc = 0.f;
            #pragma unroll
            for (int cc = 0; cc < 12; cc++)
                acc += __ldg(&l[(size_t)cc * H * W + w]) * __ldg(&r[(size_t)cc * H * W + w - d]);
            v = acc * (1.f / 12.f);
        }
    } else if (c < 20) {
        const int ch = c - 8;
        if (w >= d) v = __ldg(&c8x[((size_t)(b * 12 + ch) * H + h) * W + w]);
    } else {
        const int ch = c - 20;
        if (w >= d) v = __ldg(&c8x[((size_t)((b + 2) * 12 + ch) * H + h) * W + w - d]);
    }
    out[idx] = v;
}

// ---------------------------------------------------------------------------
extern "C" void kernel_launch(void* const* d_in, const int* in_sizes, int n_in,
                              void* d_out, int out_size)
{
    const float* gwc = (const float*)d_in[0];
    const float* cat = (const float*)d_in[1];
    const float* gw1 = (const float*)d_in[2];
    const float* gbg = (const float*)d_in[3];
    const float* gbb = (const float*)d_in[4];
    const float* gbm = (const float*)d_in[5];
    const float* gbv = (const float*)d_in[6];
    const float* gw2 = (const float*)d_in[7];
    const float* cw1 = (const float*)d_in[8];
    const float* cbg = (const float*)d_in[9];
    const float* cbb = (const float*)d_in[10];
    const float* cbm = (const float*)d_in[11];
    const float* cbv = (const float*)d_in[12];
    const float* cw2 = (const float*)d_in[13];
    float* out = (float*)d_out;

    float *y1, *mask, *g8x, *cy1, *cmask, *c8x;
    cudaGetSymbolAddress((void**)&y1,    g_y1);
    cudaGetSymbolAddress((void**)&mask,  g_mask);
    cudaGetSymbolAddress((void**)&g8x,   g_g8x);
    cudaGetSymbolAddress((void**)&cy1,   g_cy1);
    cudaGetSymbolAddress((void**)&cmask, g_cmask);
    cudaGetSymbolAddress((void**)&c8x,   g_c8x);

    const int nTiles = (4 * HW_) / 128;   // 360 (exact)

    // gwc branch
    conv_gemm_kernel<3, true><<<dim3(nTiles, 3), 256>>>(
        gwc, gw1, gbg, gbb, gbm, gbv, y1, 96, 192, 160, 288, HO_, WO_, 2, 1);
    conv_gemm_kernel<1, false><<<dim3(nTiles, 3), 256>>>(
        y1, gw2, nullptr, nullptr, nullptr, nullptr, mask, 192, 144, HO_, WO_, HO_, WO_, 1, 0);
    adaptive_ds_kernel<<<(4 * 16 * HW_ + 255) / 256, 256>>>(
        gwc, mask, g8x, 96, 16, 160, 288, 4);

    // concat branch
    conv_gemm_kernel<3, true><<<dim3(nTiles, 1), 256>>>(
        cat, cw1, cbg, cbb, cbm, cbv, cy1, 12, 24, 160, 288, HO_, WO_, 2, 1);
    conv_gemm_kernel<1, false><<<dim3(nTiles, 2), 256>>>(
        cy1, cw2, nullptr, nullptr, nullptr, nullptr, cmask, 24, 108, HO_, WO_, HO_, WO_, 1, 0);
    adaptive_ds_kernel<<<(4 * 12 * HW_ + 255) / 256, 256>>>(
        cat, cmask, c8x, 12, 12, 160, 288, 4);

    // volumes -> d_out
    build_volume_kernel<<<(2 * 32 * 24 * HW_ + 255) / 256, 256>>>(g8x, c8x, out);
}

// round 4
// speedup vs baseline: 1.2107x; 1.2107x over previous
#include <cuda_runtime.h>
#include <math.h>

// ---------------------------------------------------------------------------
//   gwc_feature (4,96,160,288)  concat_feature (4,12,160,288)
//   downsample: conv3x3 s2 p1 -> BN -> leaky(0.1) -> conv1x1 -> softmax(9)
//               -> weighted unfold sum   (HO=80, WO=144)
//   volume: D=24, gwc groups=8 (cpg=12), out (2, 32, 24, 80, 144) f32
// ---------------------------------------------------------------------------

#define HO_ 80
#define WO_ 144
#define HW_ (HO_*WO_)

typedef unsigned long long ull;

// scratch (bss, no allocation)
static __device__ float g_y1   [4*192*HW_];
static __device__ float g_mask [4*144*HW_];
static __device__ float g_g8x  [4* 96*HW_];
static __device__ float g_cy1  [4* 24*HW_];
static __device__ float g_cmask[4*108*HW_];
static __device__ float g_c8x  [4* 12*HW_];

__device__ __forceinline__ ull pack2(float lo, float hi) {
    ull r; asm("mov.b64 %0,{%1,%2};" : "=l"(r) : "f"(lo), "f"(hi)); return r;
}
__device__ __forceinline__ void unpack2(ull v, float& lo, float& hi) {
    asm("mov.b64 {%0,%1},%2;" : "=f"(lo), "=f"(hi) : "l"(v));
}
__device__ __forceinline__ void fma2(ull& d, ull a, ull b) {
    asm("fma.rn.f32x2 %0, %1, %2, %0;" : "+l"(d) : "l"(a), "l"(b));
}

// ---------------------------------------------------------------------------
// Implicit-im2col fp32 GEMM using packed f32x2 FMA.
// Tile: 64(oc) x 128(pos), BK=16, 256 threads.
// Microtile: 4 oc x 4 pos-pairs; thread l handles pos pairs {2l+32*jj}.
// Conflict-free LDS, single __syncthreads per K-tile, reg double buffering.
// Requires HW % 128 == 0 (holds: 11520).
// ---------------------------------------------------------------------------
template<int KS, bool DO_BN>
__global__ void __launch_bounds__(256)
conv_gemm_kernel(
    const float* __restrict__ x, const float* __restrict__ w,
    const float* __restrict__ bn_g, const float* __restrict__ bn_b,
    const float* __restrict__ bn_m, const float* __restrict__ bn_v,
    float* __restrict__ out,
    int Cin, int Cout, int Hin, int Win, int Hout, int Wout,
    int stride, int pad)
{
    __shared__ __align__(16) ull   As2[2][16][66];  // {a,a} pairs, [k][oc], 16B rows
    __shared__ float               Bs [2][16][128]; // [k][pos]

    const int K  = Cin * KS * KS;
    const int HW = Hout * Wout;

    const int bm = blockIdx.y * 64;
    const int bn = blockIdx.x * 128;
    const int tid = threadIdx.x;

    // ---- loader thread mapping ----
    const int akk  = tid & 15;         // A: k within tile
    const int aoc  = tid >> 4;         // A: oc base (stride 16, 4 loads)
    const int bcol = tid & 127;        // B: pos column
    const int bkb  = tid >> 7;         // B: k base (0/1, stride 2, 8 loads)

    const int posB = bn + bcol;
    const int bbB  = posB / HW;
    const int rpB  = posB - bbB * HW;
    const int hoB  = rpB / Wout;
    const int woB  = rpB - hoB * Wout;
    // precomputed input geometry for the B loader
    const int hi0 = hoB * stride - pad;
    const int wi0 = woB * stride - pad;
    const float* xbase = x + ((size_t)bbB * Cin * Hin + hi0) * Win + wi0;

    // ---- compute thread mapping ----
    const int tl = tid & 15;           // pos pair lane
    const int ty = tid >> 4;           // oc group (4 wide)

    const int nk = (K + 15) >> 4;

    float awR[4];
    float bxR[8];

    // prologue: load tile 0 into regs, STS, sync
    #pragma unroll
    for (int i = 0; i < 4; i++) {
        const int oc = bm + aoc + i * 16;
        awR[i] = (oc < Cout && akk < K) ? __ldg(&w[oc * K + akk]) : 0.f;
    }
    #pragma unroll
    for (int i = 0; i < 8; i++) {
        const int k = bkb + 2 * i;
        float v = 0.f;
        if (k < K) {
            int ic, kh, kw2;
            if (KS == 1) { ic = k; kh = 0; kw2 = 0; }
            else { ic = k / 9; int r = k - ic * 9; kh = r / 3; kw2 = r - kh * 3; }
            const int hi = hi0 + kh;
            const int wi = wi0 + kw2;
            if (hi >= 0 && hi < Hin && wi >= 0 && wi < Win)
                v = __ldg(&xbase[((size_t)ic * Hin + kh) * Win + kw2]);
        }
        bxR[i] = v;
    }
    #pragma unroll
    for (int i = 0; i < 4; i++) As2[0][akk][aoc + i * 16] = pack2(awR[i], awR[i]);
    #pragma unroll
    for (int i = 0; i < 8; i++) Bs[0][bkb + 2 * i][bcol] = bxR[i];
    __syncthreads();

    ull acc[4][4];
    #pragma unroll
    for (int i = 0; i < 4; i++)
        #pragma unroll
        for (int j = 0; j < 4; j++) acc[i][j] = 0ull;

    for (int t = 0; t < nk; t++) {
        const int cur = t & 1, nxt = cur ^ 1;
        const int k0n = (t + 1) << 4;
        const bool more = (t + 1) < nk;

        // issue global loads for next tile (consumed after compute)
        if (more) {
            #pragma unroll
            for (int i = 0; i < 4; i++) {
                const int oc = bm + aoc + i * 16;
                const int ka = k0n + akk;
                awR[i] = (oc < Cout && ka < K) ? __ldg(&w[oc * K + ka]) : 0.f;
            }
            #pragma unroll
            for (int i = 0; i < 8; i++) {
                const int k = k0n + bkb + 2 * i;
                float v = 0.f;
                if (k < K) {
                    int ic, kh, kw2;
                    if (KS == 1) { ic = k; kh = 0; kw2 = 0; }
                    else { ic = k / 9; int r = k - ic * 9; kh = r / 3; kw2 = r - kh * 3; }
                    const int hi = hi0 + kh;
                    const int wi = wi0 + kw2;
                    if (hi >= 0 && hi < Hin && wi >= 0 && wi < Win)
                        v = __ldg(&xbase[((size_t)ic * Hin + kh) * Win + kw2]);
                }
                bxR[i] = v;
            }
        }

        // compute over current buffer (conflict-free LDS)
        #pragma unroll
        for (int kk = 0; kk < 16; kk++) {
            const ulonglong2 a01 = *reinterpret_cast<const ulonglong2*>(&As2[cur][kk][ty * 4]);
            const ulonglong2 a23 = *reinterpret_cast<const ulonglong2*>(&As2[cur][kk][ty * 4 + 2]);
            const float* brow = &Bs[cur][kk][2 * tl];
            ull c0 = *reinterpret_cast<const ull*>(brow);
            ull c1 = *reinterpret_cast<const ull*>(brow + 32);
            ull c2 = *reinterpret_cast<const ull*>(brow + 64);
            ull c3 = *reinterpret_cast<const ull*>(brow + 96);
            fma2(acc[0][0], a01.x, c0); fma2(acc[0][1], a01.x, c1);
            fma2(acc[0][2], a01.x, c2); fma2(acc[0][3], a01.x, c3);
            fma2(acc[1][0], a01.y, c0); fma2(acc[1][1], a01.y, c1);
            fma2(acc[1][2], a01.y, c2); fma2(acc[1][3], a01.y, c3);
            fma2(acc[2][0], a23.x, c0); fma2(acc[2][1], a23.x, c1);
            fma2(acc[2][2], a23.x, c2); fma2(acc[2][3], a23.x, c3);
            fma2(acc[3][0], a23.y, c0); fma2(acc[3][1], a23.y, c1);
            fma2(acc[3][2], a23.y, c2); fma2(acc[3][3], a23.y, c3);
        }

        // stage next tile; single barrier per iteration
        if (more) {
            #pragma unroll
            for (int i = 0; i < 4; i++) As2[nxt][akk][aoc + i * 16] = pack2(awR[i], awR[i]);
            #pragma unroll
            for (int i = 0; i < 8; i++) Bs[nxt][bkb + 2 * i][bcol] = bxR[i];
            __syncthreads();
        }
    }

    // epilogue: all 128 pos in this tile share one batch index
    const int posb0 = bn + 2 * tl;
    const int bb  = posb0 / HW;
    const int rp0 = posb0 - bb * HW;

    #pragma unroll
    for (int i = 0; i < 4; i++) {
        const int oc = bm + ty * 4 + i;
        if (oc >= Cout) continue;
        float scale = 1.f, bias = 0.f;
        if (DO_BN) {
            const float s = bn_g[oc] * rsqrtf(bn_v[oc] + 1e-5f);
            scale = s;
            bias  = bn_b[oc] - bn_m[oc] * s;
        }
        float* orow = out + (size_t)(bb * Cout + oc) * HW + rp0;
        #pragma unroll
        for (int j = 0; j < 4; j++) {
            float v0, v1;
            unpack2(acc[i][j], v0, v1);
            if (DO_BN) {
                v0 = v0 * scale + bias;  v0 = (v0 >= 0.f) ? v0 : 0.1f * v0;
                v1 = v1 * scale + bias;  v1 = (v1 >= 0.f) ? v1 : 0.1f * v1;
            }
            float2 vv; vv.x = v0; vv.y = v1;
            *reinterpret_cast<float2*>(&orow[32 * j]) = vv;
        }
    }
}

// ---------------------------------------------------------------------------
// Fused: softmax over 9 logits per (b, group, ho, wo), then weighted unfold
// sum over the 3x3 stride-2 patch. Channel for (i, g) is ch = i*G + g.
// ---------------------------------------------------------------------------
__global__ void adaptive_ds_kernel(
    const float* __restrict__ x, const float* __restrict__ logits,
    float* __restrict__ out,
    int Cin, int G, int Hin, int Win, int Bsz)
{
    const int idx = blockIdx.x * blockDim.x + threadIdx.x;
    const int total = Bsz * G * HW_;
    if (idx >= total) return;

    const int wo = idx % WO_;
    int t = idx / WO_;
    const int ho = t % HO_;  t /= HO_;
    const int g  = t % G;
    const int b  = t / G;

    float lg[9];
    float mx = -1e30f;
    const size_t lbase = ((size_t)(b * G * 9 + g * 9) * HW_) + ho * WO_ + wo;
    #pragma unroll
    for (int k = 0; k < 9; k++) {
        lg[k] = logits[lbase + (size_t)k * HW_];
        mx = fmaxf(mx, lg[k]);
    }
    float s = 0.f;
    #pragma unroll
    for (int k = 0; k < 9; k++) { lg[k] = __expf(lg[k] - mx); s += lg[k]; }
    const float inv = 1.f / s;
    #pragma unroll
    for (int k = 0; k < 9; k++) lg[k] *= inv;

    const int cpg = Cin / G;
    for (int i = 0; i < cpg; i++) {
        const int ch = i * G + g;
        const float* xb = x + (size_t)(b * Cin + ch) * Hin * Win;
        float acc = 0.f;
        #pragma unroll
        for (int kh = 0; kh < 3; kh++) {
            const int hi = 2 * ho + kh - 1;
            if (hi < 0 || hi >= Hin) continue;
            #pragma unroll
            for (int kw = 0; kw < 3; kw++) {
                const int wi = 2 * wo + kw - 1;
                if (wi < 0 || wi >= Win) continue;
                acc += lg[kh * 3 + kw] * __ldg(&xb[(size_t)hi * Win + wi]);
            }
        }
        out[((size_t)(b * Cin + ch) * HW_) + ho * WO_ + wo] = acc;
    }
}

// ---------------------------------------------------------------------------
// Cost volumes. Output (2, 32, 24, 80, 144):
//   c in [0,8):   gwc corr  mean_{cc<12} l[g*12+cc][w] * r[g*12+cc][w-d]
//   c in [8,20):  l_c[c-8][w]       if w>=d else 0
//   c in [20,32): r_c[c-20][w-d]    if w>=d else 0
// ---------------------------------------------------------------------------
__global__ void build_volume_kernel(
    const float* __restrict__ g8x, const float* __restrict__ c8x,
    float* __restrict__ out)
{
    const int W = WO_, H = HO_, D = 24, OC = 32;
    const int total = 2 * OC * D * H * W;
    const int idx = blockIdx.x * blockDim.x + threadIdx.x;
    if (idx >= total) return;

    const int w = idx % W;
    int t = idx / W;
    const int h = t % H;  t /= H;
    const int d = t % D;  t /= D;
    const int c = t % OC;
    const int b = t / OC;

    float v = 0.f;
    if (c < 8) {
        if (w >= d) {
            const float* l = g8x + ((size_t)(b       * 96 + c * 12) * H + h) * W;
            const float* r = g8x + ((size_t)((b + 2) * 96 + c * 12) * H + h) * W;
            float acc = 0.f;
            #pragma unroll
            for (int cc = 0; cc < 12; cc++)
                acc += __ldg(&l[(size_t)cc * H * W + w]) * __ldg(&r[(size_t)cc * H * W + w - d]);
            v = acc * (1.f / 12.f);
        }
    } else if (c < 20) {
        const int ch = c - 8;
        if (w >= d) v = __ldg(&c8x[((size_t)(b * 12 + ch) * H + h) * W + w]);
    } else {
        const int ch = c - 20;
        if (w >= d) v = __ldg(&c8x[((size_t)((b + 2) * 12 + ch) * H + h) * W + w - d]);
    }
    out[idx] = v;
}

// ---------------------------------------------------------------------------
extern "C" void kernel_launch(void* const* d_in, const int* in_sizes, int n_in,
                              void* d_out, int out_size)
{
    const float* gwc = (const float*)d_in[0];
    const float* cat = (const float*)d_in[1];
    const float* gw1 = (const float*)d_in[2];
    const float* gbg = (const float*)d_in[3];
    const float* gbb = (const float*)d_in[4];
    const float* gbm = (const float*)d_in[5];
    const float* gbv = (const float*)d_in[6];
    const float* gw2 = (const float*)d_in[7];
    const float* cw1 = (const float*)d_in[8];
    const float* cbg = (const float*)d_in[9];
    const float* cbb = (const float*)d_in[10];
    const float* cbm = (const float*)d_in[11];
    const float* cbv = (const float*)d_in[12];
    const float* cw2 = (const float*)d_in[13];
    float* out = (float*)d_out;

    float *y1, *mask, *g8x, *cy1, *cmask, *c8x;
    cudaGetSymbolAddress((void**)&y1,    g_y1);
    cudaGetSymbolAddress((void**)&mask,  g_mask);
    cudaGetSymbolAddress((void**)&g8x,   g_g8x);
    cudaGetSymbolAddress((void**)&cy1,   g_cy1);
    cudaGetSymbolAddress((void**)&cmask, g_cmask);
    cudaGetSymbolAddress((void**)&c8x,   g_c8x);

    const int nTiles = (4 * HW_) / 128;   // 360 (exact)

    // gwc branch
    conv_gemm_kernel<3, true><<<dim3(nTiles, 3), 256>>>(
        gwc, gw1, gbg, gbb, gbm, gbv, y1, 96, 192, 160, 288, HO_, WO_, 2, 1);
    conv_gemm_kernel<1, false><<<dim3(nTiles, 3), 256>>>(
        y1, gw2, nullptr, nullptr, nullptr, nullptr, mask, 192, 144, HO_, WO_, HO_, WO_, 1, 0);
    adaptive_ds_kernel<<<(4 * 16 * HW_ + 255) / 256, 256>>>(
        gwc, mask, g8x, 96, 16, 160, 288, 4);

    // concat branch
    conv_gemm_kernel<3, true><<<dim3(nTiles, 1), 256>>>(
        cat, cw1, cbg, cbb, cbm, cbv, cy1, 12, 24, 160, 288, HO_, WO_, 2, 1);
    conv_gemm_kernel<1, false><<<dim3(nTiles, 2), 256>>>(
        cy1, cw2, nullptr, nullptr, nullptr, nullptr, cmask, 24, 108, HO_, WO_, HO_, WO_, 1, 0);
    adaptive_ds_kernel<<<(4 * 12 * HW_ + 255) / 256, 256>>>(
        cat, cmask, c8x, 12, 12, 160, 288, 4);

    // volumes -> d_out
    build_volume_kernel<<<(2 * 32 * 24 * HW_ + 255) / 256, 256>>>(g8x, c8x, out);
}

// round 5
// speedup vs baseline: 1.2125x; 1.0015x over previous
#include <cuda_runtime.h>
#include <math.h>
#include <stdint.h>

// ---------------------------------------------------------------------------
//   gwc_feature (4,96,160,288)  concat_feature (4,12,160,288)
//   downsample: conv3x3 s2 p1 -> BN -> leaky(0.1) -> conv1x1 -> softmax(9)
//               -> weighted unfold sum   (HO=80, WO=144)
//   volume: D=24, gwc groups=8 (cpg=12), out (2, 32, 24, 80, 144) f32
// ---------------------------------------------------------------------------

#define HO_ 80
#define WO_ 144
#define HW_ (HO_*WO_)

// scratch (bss, no allocation)
static __device__ float g_y1   [4*192*HW_];
static __device__ float g_mask [4*144*HW_];
static __device__ float g_g8x  [4* 96*HW_];
static __device__ float g_cy1  [4* 24*HW_];
static __device__ float g_cmask[4*108*HW_];
static __device__ float g_c8x  [4* 12*HW_];

__device__ __forceinline__ uint32_t f2tf32(float v) {
    uint32_t r; asm("cvt.rna.tf32.f32 %0, %1;" : "=r"(r) : "f"(v)); return r;
}
__device__ __forceinline__ void mma_tf32(float* c, const uint32_t* a, const uint32_t* b) {
    asm volatile(
        "mma.sync.aligned.m16n8k8.row.col.f32.tf32.tf32.f32 "
        "{%0,%1,%2,%3}, {%4,%5,%6,%7}, {%8,%9}, {%0,%1,%2,%3};"
        : "+f"(c[0]), "+f"(c[1]), "+f"(c[2]), "+f"(c[3])
        : "r"(a[0]), "r"(a[1]), "r"(a[2]), "r"(a[3]), "r"(b[0]), "r"(b[1]));
}

// ---------------------------------------------------------------------------
// Implicit-im2col GEMM on tensor cores (tf32 3x split = fp32-grade).
// Block 256 thr, tile 64(oc) x 128(pos), BK=16 (2 mma k-steps).
// 8 warps as 2(M) x 4(N); warp tile 32x32 = 2x4 m16n8k8 tiles.
// smem holds hi/lo tf32 planes in per-lane FRAGMENT order:
//   A: idx = ((s*4+mtile)*32 + lane)*4 + reg      (reg: a0..a3)
//   B: idx = ((s*16+ntile)*32 + lane)*2 + reg     (reg: b0,b1)
// Fragment maps (PTX m16n8k8.tf32): g=lane>>2, tg=lane&3
//   A: a0(g,tg) a1(g+8,tg) a2(g,tg+4) a3(g+8,tg+4)
//   B: b0(tg,n=g) b1(tg+4,g)     C: c0(g,2tg) c1(g,2tg+1) c2(g+8,2tg) c3(g+8,2tg+1)
// Requires HW % 128 == 0 (11520: ok).
// ---------------------------------------------------------------------------
template<int KS, bool DO_BN>
__global__ void __launch_bounds__(256)
conv_mma_kernel(
    const float* __restrict__ x, const float* __restrict__ w,
    const float* __restrict__ bn_g, const float* __restrict__ bn_b,
    const float* __restrict__ bn_m, const float* __restrict__ bn_v,
    float* __restrict__ out,
    int Cin, int Cout, int Hin, int Win, int Hout, int Wout,
    int stride, int pad)
{
    __shared__ __align__(16) uint32_t As[2][2048];  // [buf][hi:0..1023 | lo:1024..]
    __shared__ __align__(16) uint32_t Bs[2][4096];  // [buf][hi:0..2047 | lo:2048..]

    const int K  = Cin * KS * KS;
    const int HW = Hout * Wout;
    const int bm = blockIdx.y * 64;
    const int bn = blockIdx.x * 128;
    const int tid = threadIdx.x;

    // ---- A loader: thread -> (kA, ocA); 4 elems at oc = ocA + 16*i ----
    const int kA  = tid & 15;
    const int ocA = tid >> 4;
    int aidx[4];
    {
        const int s = kA >> 3, kk = kA & 7;
        #pragma unroll
        for (int i = 0; i < 4; i++)
            aidx[i] = ((s * 4 + i) * 32 + (ocA & 7) * 4 + (kk & 3)) * 4
                      + (kk >> 2) * 2 + (ocA >> 3);
    }

    // ---- B loader: thread -> (posL, kB0); 8 elems at k = kB0 + 2*i ----
    const int posL = tid & 127;
    const int kB0  = tid >> 7;
    const int posB = bn + posL;
    const int bbB  = posB / HW;
    const int rpB  = posB - bbB * HW;
    const int hoB  = rpB / Wout;
    const int woB  = rpB - hoB * Wout;
    const int hi0  = hoB * stride - pad;
    const int wi0  = woB * stride - pad;
    const float* xbase = x + ((size_t)bbB * Cin * Hin + hi0) * Win + wi0;
    int bidx[8];
    {
        const int n = posL >> 3, col = posL & 7;
        #pragma unroll
        for (int i = 0; i < 8; i++) {
            const int kl = kB0 + 2 * i;
            const int s = kl >> 3, kk = kl & 7;
            bidx[i] = ((s * 16 + n) * 32 + col * 4 + (kk & 3)) * 2 + (kk >> 2);
        }
    }

    const int nk = (K + 15) >> 4;

    float awR[4], bxR[8];

    auto loadA = [&](int k0) {
        #pragma unroll
        for (int i = 0; i < 4; i++) {
            const int oc = bm + ocA + 16 * i;
            const int k  = k0 + kA;
            awR[i] = (oc < Cout && k < K) ? __ldg(&w[oc * K + k]) : 0.f;
        }
    };
    auto loadB = [&](int k0) {
        #pragma unroll
        for (int i = 0; i < 8; i++) {
            const int k = k0 + kB0 + 2 * i;
            float v = 0.f;
            if (k < K) {
                int ic, kh, kw2;
                if (KS == 1) { ic = k; kh = 0; kw2 = 0; }
                else { ic = k / 9; int r = k - ic * 9; kh = r / 3; kw2 = r - kh * 3; }
                const int hi = hi0 + kh;
                const int wi = wi0 + kw2;
                if (hi >= 0 && hi < Hin && wi >= 0 && wi < Win)
                    v = __ldg(&xbase[((size_t)ic * Hin + kh) * Win + kw2]);
            }
            bxR[i] = v;
        }
    };
    auto storeTile = [&](int buf) {
        #pragma unroll
        for (int i = 0; i < 4; i++) {
            const uint32_t h = f2tf32(awR[i]);
            const uint32_t l = f2tf32(awR[i] - __uint_as_float(h));
            As[buf][aidx[i]] = h;
            As[buf][1024 + aidx[i]] = l;
        }
        #pragma unroll
        for (int i = 0; i < 8; i++) {
            const uint32_t h = f2tf32(bxR[i]);
            const uint32_t l = f2tf32(bxR[i] - __uint_as_float(h));
            Bs[buf][bidx[i]] = h;
            Bs[buf][2048 + bidx[i]] = l;
        }
    };

    // prologue
    loadA(0); loadB(0);
    storeTile(0);
    __syncthreads();

    // ---- compute mapping ----
    const int warp = tid >> 5, lane = tid & 31;
    const int wm = warp >> 2, wn = warp & 3;

    float acc[2][4][4];
    #pragma unroll
    for (int mt = 0; mt < 2; mt++)
        #pragma unroll
        for (int nt = 0; nt < 4; nt++)
            #pragma unroll
            for (int r = 0; r < 4; r++) acc[mt][nt][r] = 0.f;

    for (int t = 0; t < nk; t++) {
        const int cur = t & 1, nxt = cur ^ 1;
        const bool more = (t + 1) < nk;
        if (more) { loadA((t + 1) << 4); loadB((t + 1) << 4); }

        #pragma unroll
        for (int s = 0; s < 2; s++) {
            uint32_t ah[2][4], al[2][4];
            #pragma unroll
            for (int mt = 0; mt < 2; mt++) {
                const int base = ((s * 4 + wm * 2 + mt) * 32 + lane) * 4;
                *reinterpret_cast<uint4*>(ah[mt]) = *reinterpret_cast<const uint4*>(&As[cur][base]);
                *reinterpret_cast<uint4*>(al[mt]) = *reinterpret_cast<const uint4*>(&As[cur][1024 + base]);
            }
            uint32_t bh[4][2], bl[4][2];
            #pragma unroll
            for (int nt = 0; nt < 4; nt++) {
                const int base = ((s * 16 + wn * 4 + nt) * 32 + lane) * 2;
                *reinterpret_cast<uint2*>(bh[nt]) = *reinterpret_cast<const uint2*>(&Bs[cur][base]);
                *reinterpret_cast<uint2*>(bl[nt]) = *reinterpret_cast<const uint2*>(&Bs[cur][2048 + base]);
            }
            #pragma unroll
            for (int mt = 0; mt < 2; mt++)
                #pragma unroll
                for (int nt = 0; nt < 4; nt++) {
                    mma_tf32(acc[mt][nt], ah[mt], bh[nt]);
                    mma_tf32(acc[mt][nt], ah[mt], bl[nt]);
                    mma_tf32(acc[mt][nt], al[mt], bh[nt]);
                }
        }

        if (more) {
            storeTile(nxt);
            __syncthreads();
        }
    }

    // ---- epilogue ----
    const int g  = lane >> 2;
    const int tg = lane & 3;
    const int bb  = bn / HW;                 // whole block shares one batch
    const int rp0 = bn - bb * HW;

    #pragma unroll
    for (int mt = 0; mt < 2; mt++) {
        #pragma unroll
        for (int half = 0; half < 2; half++) {     // c0,c1 vs c2,c3
            const int oc = bm + wm * 32 + mt * 16 + g + half * 8;
            if (oc >= Cout) continue;
            float scale = 1.f, bias = 0.f;
            if (DO_BN) {
                const float s = bn_g[oc] * rsqrtf(bn_v[oc] + 1e-5f);
                scale = s;
                bias  = bn_b[oc] - bn_m[oc] * s;
            }
            float* orow = out + (size_t)(bb * Cout + oc) * HW + rp0;
            #pragma unroll
            for (int nt = 0; nt < 4; nt++) {
                const int pc = wn * 32 + nt * 8 + 2 * tg;
                float v0 = acc[mt][nt][half * 2 + 0];
                float v1 = acc[mt][nt][half * 2 + 1];
                if (DO_BN) {
                    v0 = v0 * scale + bias;  v0 = (v0 >= 0.f) ? v0 : 0.1f * v0;
                    v1 = v1 * scale + bias;  v1 = (v1 >= 0.f) ? v1 : 0.1f * v1;
                }
                float2 vv; vv.x = v0; vv.y = v1;
                *reinterpret_cast<float2*>(&orow[pc]) = vv;
            }
        }
    }
}

// ---------------------------------------------------------------------------
// Fused: softmax over 9 logits per (b, group, ho, wo), then weighted unfold
// sum over the 3x3 stride-2 patch. Channel for (i, g) is ch = i*G + g.
// ---------------------------------------------------------------------------
__global__ void adaptive_ds_kernel(
    const float* __restrict__ x, const float* __restrict__ logits,
    float* __restrict__ out,
    int Cin, int G, int Hin, int Win, int Bsz)
{
    const int idx = blockIdx.x * blockDim.x + threadIdx.x;
    const int total = Bsz * G * HW_;
    if (idx >= total) return;

    const int wo = idx % WO_;
    int t = idx / WO_;
    const int ho = t % HO_;  t /= HO_;
    const int g  = t % G;
    const int b  = t / G;

    float lg[9];
    float mx = -1e30f;
    const size_t lbase = ((size_t)(b * G * 9 + g * 9) * HW_) + ho * WO_ + wo;
    #pragma unroll
    for (int k = 0; k < 9; k++) {
        lg[k] = logits[lbase + (size_t)k * HW_];
        mx = fmaxf(mx, lg[k]);
    }
    float s = 0.f;
    #pragma unroll
    for (int k = 0; k < 9; k++) { lg[k] = __expf(lg[k] - mx); s += lg[k]; }
    const float inv = 1.f / s;
    #pragma unroll
    for (int k = 0; k < 9; k++) lg[k] *= inv;

    const int cpg = Cin / G;
    for (int i = 0; i < cpg; i++) {
        const int ch = i * G + g;
        const float* xb = x + (size_t)(b * Cin + ch) * Hin * Win;
        float acc = 0.f;
        #pragma unroll
        for (int kh = 0; kh < 3; kh++) {
            const int hi = 2 * ho + kh - 1;
            if (hi < 0 || hi >= Hin) continue;
            #pragma unroll
            for (int kw = 0; kw < 3; kw++) {
                const int wi = 2 * wo + kw - 1;
                if (wi < 0 || wi >= Win) continue;
                acc += lg[kh * 3 + kw] * __ldg(&xb[(size_t)hi * Win + wi]);
            }
        }
        out[((size_t)(b * Cin + ch) * HW_) + ho * WO_ + wo] = acc;
    }
}

// ---------------------------------------------------------------------------
// Cost volumes. Output (2, 32, 24, 80, 144):
//   c in [0,8):   gwc corr  mean_{cc<12} l[g*12+cc][w] * r[g*12+cc][w-d]
//   c in [8,20):  l_c[c-8][w]       if w>=d else 0
//   c in [20,32): r_c[c-20][w-d]    if w>=d else 0
// ---------------------------------------------------------------------------
__global__ void build_volume_kernel(
    const float* __restrict__ g8x, const float* __restrict__ c8x,
    float* __restrict__ out)
{
    const int W = WO_, H = HO_, D = 24, OC = 32;
    const int total = 2 * OC * D * H * W;
    const int idx = blockIdx.x * blockDim.x + threadIdx.x;
    if (idx >= total) return;

    const int w = idx % W;
    int t = idx / W;
    const int h = t % H;  t /= H;
    const int d = t % D;  t /= D;
    const int c = t % OC;
    const int b = t / OC;

    float v = 0.f;
    if (c < 8) {
        if (w >= d) {
            const float* l = g8x + ((size_t)(b       * 96 + c * 12) * H + h) * W;
            const float* r = g8x + ((size_t)((b + 2) * 96 + c * 12) * H + h) * W;
            float acc = 0.f;
            #pragma unroll
            for (int cc = 0; cc < 12; cc++)
                acc += __ldg(&l[(size_t)cc * H * W + w]) * __ldg(&r[(size_t)cc * H * W + w - d]);
            v = acc * (1.f / 12.f);
        }
    } else if (c < 20) {
        const int ch = c - 8;
        if (w >= d) v = __ldg(&c8x[((size_t)(b * 12 + ch) * H + h) * W + w]);
    } else {
        const int ch = c - 20;
        if (w >= d) v = __ldg(&c8x[((size_t)((b + 2) * 12 + ch) * H + h) * W + w - d]);
    }
    out[idx] = v;
}

// ---------------------------------------------------------------------------
extern "C" void kernel_launch(void* const* d_in, const int* in_sizes, int n_in,
                              void* d_out, int out_size)
{
    const float* gwc = (const float*)d_in[0];
    const float* cat = (const float*)d_in[1];
    const float* gw1 = (const float*)d_in[2];
    const float* gbg = (const float*)d_in[3];
    const float* gbb = (const float*)d_in[4];
    const float* gbm = (const float*)d_in[5];
    const float* gbv = (const float*)d_in[6];
    const float* gw2 = (const float*)d_in[7];
    const float* cw1 = (const float*)d_in[8];
    const float* cbg = (const float*)d_in[9];
    const float* cbb = (const float*)d_in[10];
    const float* cbm = (const float*)d_in[11];
    const float* cbv = (const float*)d_in[12];
    const float* cw2 = (const float*)d_in[13];
    float* out = (float*)d_out;

    float *y1, *mask, *g8x, *cy1, *cmask, *c8x;
    cudaGetSymbolAddress((void**)&y1,    g_y1);
    cudaGetSymbolAddress((void**)&mask,  g_mask);
    cudaGetSymbolAddress((void**)&g8x,   g_g8x);
    cudaGetSymbolAddress((void**)&cy1,   g_cy1);
    cudaGetSymbolAddress((void**)&cmask, g_cmask);
    cudaGetSymbolAddress((void**)&c8x,   g_c8x);

    const int nTiles = (4 * HW_) / 128;   // 360 (exact)

    // gwc branch
    conv_mma_kernel<3, true><<<dim3(nTiles, 3), 256>>>(
        gwc, gw1, gbg, gbb, gbm, gbv, y1, 96, 192, 160, 288, HO_, WO_, 2, 1);
    conv_mma_kernel<1, false><<<dim3(nTiles, 3), 256>>>(
        y1, gw2, nullptr, nullptr, nullptr, nullptr, mask, 192, 144, HO_, WO_, HO_, WO_, 1, 0);
    adaptive_ds_kernel<<<(4 * 16 * HW_ + 255) / 256, 256>>>(
        gwc, mask, g8x, 96, 16, 160, 288, 4);

    // concat branch
    conv_mma_kernel<3, true><<<dim3(nTiles, 1), 256>>>(
        cat, cw1, cbg, cbb, cbm, cbv, cy1, 12, 24, 160, 288, HO_, WO_, 2, 1);
    conv_mma_kernel<1, false><<<dim3(nTiles, 2), 256>>>(
        cy1, cw2, nullptr, nullptr, nullptr, nullptr, cmask, 24, 108, HO_, WO_, HO_, WO_, 1, 0);
    adaptive_ds_kernel<<<(4 * 12 * HW_ + 255) / 256, 256>>>(
        cat, cmask, c8x, 12, 12, 160, 288, 4);

    // volumes -> d_out
    build_volume_kernel<<<(2 * 32 * 24 * HW_ + 255) / 256, 256>>>(g8x, c8x, out);
}

// round 6
// speedup vs baseline: 1.6404x; 1.3529x over previous
#include <cuda_runtime.h>
#include <math.h>
#include <stdint.h>

// ---------------------------------------------------------------------------
//   gwc_feature (4,96,160,288)  concat_feature (4,12,160,288)
//   downsample: conv3x3 s2 p1 -> BN -> leaky(0.1) -> conv1x1 -> softmax(9)
//               -> weighted unfold sum   (HO=80, WO=144)
//   volume: D=24, gwc groups=8 (cpg=12), out (2, 32, 24, 80, 144) f32
// ---------------------------------------------------------------------------

#define HO_ 80
#define WO_ 144
#define HW_ (HO_*WO_)

// scratch (bss, no allocation)
static __device__ float g_y1   [4*192*HW_];
static __device__ float g_mask [4*144*HW_];
static __device__ float g_g8x  [4* 96*HW_];
static __device__ float g_cy1  [4* 24*HW_];
static __device__ float g_cmask[4*108*HW_];
static __device__ float g_c8x  [4* 12*HW_];

// Split (x0,x1) into packed bf16x2 hi and residual lo. Low k in low 16 bits.
// PTX cvt.rn.bf16x2.f32 d, a, b  ->  d = {hi: a, lo: b}
__device__ __forceinline__ uint2 split2(float x0, float x1) {
    uint32_t h;
    asm("cvt.rn.bf16x2.f32 %0, %1, %2;" : "=r"(h) : "f"(x1), "f"(x0));
    const float h0 = __uint_as_float(h << 16);
    const float h1 = __uint_as_float(h & 0xffff0000u);
    uint32_t l;
    asm("cvt.rn.bf16x2.f32 %0, %1, %2;" : "=r"(l) : "f"(x1 - h1), "f"(x0 - h0));
    uint2 r; r.x = h; r.y = l; return r;
}

__device__ __forceinline__ void mma_bf16(float* c, const uint32_t* a, const uint32_t* b) {
    asm volatile(
        "mma.sync.aligned.m16n8k16.row.col.f32.bf16.bf16.f32 "
        "{%0,%1,%2,%3}, {%4,%5,%6,%7}, {%8,%9}, {%0,%1,%2,%3};"
        : "+f"(c[0]), "+f"(c[1]), "+f"(c[2]), "+f"(c[3])
        : "r"(a[0]), "r"(a[1]), "r"(a[2]), "r"(a[3]), "r"(b[0]), "r"(b[1]));
}

// ---------------------------------------------------------------------------
// Implicit-im2col GEMM on tensor cores, bf16 2-split (hh + hl + lh) =
// ~1e-5 relative accuracy, fp32 accumulate.
// Block 256 thr, tile 64(oc) x 128(pos), BK=16 (one m16n8k16 k-step).
// 8 warps as 2(M) x 4(N); warp tile 32x32 = 2x4 mma tiles.
// smem: natural [kpair][col] layout, {hi,lo} packed per uint2.
//   Ap row stride 68, Bp row stride 132  ->  2R mod 32 = 8: fragment LDS.64
//   banks are (8*tg + 2*g) per 16-lane phase: conflict-free.
// Fragment maps (m16n8k16): g=lane>>2, tg=lane&3
//   A: a0(g, kp=tg) a1(g+8, tg) a2(g, tg+4) a3(g+8, tg+4)
//   B: b0(kp=tg, n=g) b1(tg+4, g)
//   C: c0(g,2tg) c1(g,2tg+1) c2(g+8,2tg) c3(g+8,2tg+1)
// Requires HW % 128 == 0 (11520: ok), K even (holds).
// ---------------------------------------------------------------------------
template<int KS, bool DO_BN>
__global__ void __launch_bounds__(256)
conv_mma_kernel(
    const float* __restrict__ x, const float* __restrict__ w,
    const float* __restrict__ bn_g, const float* __restrict__ bn_b,
    const float* __restrict__ bn_m, const float* __restrict__ bn_v,
    float* __restrict__ out,
    int Cin, int Cout, int Hin, int Win, int Hout, int Wout,
    int stride, int pad)
{
    __shared__ __align__(16) uint2 Ap[2][8][68];   // [buf][kpair][oc]
    __shared__ __align__(16) uint2 Bp[2][8][132];  // [buf][kpair][pos]

    const int K  = Cin * KS * KS;
    const int HW = Hout * Wout;
    const int bm = blockIdx.y * 64;
    const int bn = blockIdx.x * 128;
    const int tid = threadIdx.x;

    // ---- A loader: thread -> (kpair, oc, oc+32) ----
    const int kpA = tid & 7;
    const int ocA = tid >> 3;          // 0..31

    // ---- B loader: thread -> (pos, kpair base) ----
    const int posL = tid & 127;
    const int kpB  = tid >> 7;         // 0..1; kpairs kpB, kpB+2, kpB+4, kpB+6
    const int posB = bn + posL;
    const int bbB  = posB / HW;
    const int rpB  = posB - bbB * HW;
    const int hoB  = rpB / Wout;
    const int woB  = rpB - hoB * Wout;
    const int hi0  = hoB * stride - pad;
    const int wi0  = woB * stride - pad;
    const float* xbase = x + ((size_t)bbB * Cin * Hin + hi0) * Win + wi0;

    const int nk = (K + 15) >> 4;

    float2 awR[2];
    float  bxR[8];

    auto loadA = [&](int k0) {
        const int k = k0 + 2 * kpA;
        #pragma unroll
        for (int i = 0; i < 2; i++) {
            const int oc = bm + ocA + 32 * i;
            if (oc < Cout && k < K)
                awR[i] = *reinterpret_cast<const float2*>(&w[(size_t)oc * K + k]);
            else { awR[i].x = 0.f; awR[i].y = 0.f; }
        }
    };
    auto loadB = [&](int k0) {
        #pragma unroll
        for (int i = 0; i < 4; i++) {
            const int kp = kpB + 2 * i;
            #pragma unroll
            for (int j = 0; j < 2; j++) {
                const int k = k0 + 2 * kp + j;
                float v = 0.f;
                if (k < K) {
                    int ic, kh, kw2;
                    if (KS == 1) { ic = k; kh = 0; kw2 = 0; }
                    else { ic = k / 9; int r = k - ic * 9; kh = r / 3; kw2 = r - kh * 3; }
                    const int hi = hi0 + kh;
                    const int wi = wi0 + kw2;
                    if (hi >= 0 && hi < Hin && wi >= 0 && wi < Win)
                        v = __ldg(&xbase[((size_t)ic * Hin + kh) * Win + kw2]);
                }
                bxR[2 * i + j] = v;
            }
        }
    };
    auto storeTile = [&](int buf) {
        #pragma unroll
        for (int i = 0; i < 2; i++)
            Ap[buf][kpA][ocA + 32 * i] = split2(awR[i].x, awR[i].y);
        #pragma unroll
        for (int i = 0; i < 4; i++)
            Bp[buf][kpB + 2 * i][posL] = split2(bxR[2 * i], bxR[2 * i + 1]);
    };

    // prologue
    loadA(0); loadB(0);
    storeTile(0);
    __syncthreads();

    // ---- compute mapping ----
    const int warp = tid >> 5, lane = tid & 31;
    const int wm = warp >> 2, wn = warp & 3;
    const int g  = lane >> 2, tg = lane & 3;

    float acc[2][4][4];
    #pragma unroll
    for (int mt = 0; mt < 2; mt++)
        #pragma unroll
        for (int nt = 0; nt < 4; nt++)
            #pragma unroll
            for (int r = 0; r < 4; r++) acc[mt][nt][r] = 0.f;

    for (int t = 0; t < nk; t++) {
        const int cur = t & 1, nxt = cur ^ 1;
        const bool more = (t + 1) < nk;
        if (more) { loadA((t + 1) << 4); loadB((t + 1) << 4); }

        uint32_t ah[2][4], al[2][4];
        #pragma unroll
        for (int mt = 0; mt < 2; mt++) {
            const int ob = wm * 32 + mt * 16 + g;
            const uint2 q0 = Ap[cur][tg    ][ob    ];
            const uint2 q1 = Ap[cur][tg    ][ob + 8];
            const uint2 q2 = Ap[cur][tg + 4][ob    ];
            const uint2 q3 = Ap[cur][tg + 4][ob + 8];
            ah[mt][0] = q0.x; ah[mt][1] = q1.x; ah[mt][2] = q2.x; ah[mt][3] = q3.x;
            al[mt][0] = q0.y; al[mt][1] = q1.y; al[mt][2] = q2.y; al[mt][3] = q3.y;
        }
        uint32_t bh[4][2], bl[4][2];
        #pragma unroll
        for (int nt = 0; nt < 4; nt++) {
            const int pb = wn * 32 + nt * 8 + g;
            const uint2 r0 = Bp[cur][tg    ][pb];
            const uint2 r1 = Bp[cur][tg + 4][pb];
            bh[nt][0] = r0.x; bh[nt][1] = r1.x;
            bl[nt][0] = r0.y; bl[nt][1] = r1.y;
        }
        #pragma unroll
        for (int mt = 0; mt < 2; mt++)
            #pragma unroll
            for (int nt = 0; nt < 4; nt++) {
                mma_bf16(acc[mt][nt], ah[mt], bh[nt]);
                mma_bf16(acc[mt][nt], ah[mt], bl[nt]);
                mma_bf16(acc[mt][nt], al[mt], bh[nt]);
            }

        if (more) {
            storeTile(nxt);
            __syncthreads();
        }
    }

    // ---- epilogue (C fragment layout as in round 5; verified) ----
    const int bb  = bn / HW;                 // whole block shares one batch
    const int rp0 = bn - bb * HW;

    #pragma unroll
    for (int mt = 0; mt < 2; mt++) {
        #pragma unroll
        for (int half = 0; half < 2; half++) {
            const int oc = bm + wm * 32 + mt * 16 + g + half * 8;
            if (oc >= Cout) continue;
            float scale = 1.f, bias = 0.f;
            if (DO_BN) {
                const float s = bn_g[oc] * rsqrtf(bn_v[oc] + 1e-5f);
                scale = s;
                bias  = bn_b[oc] - bn_m[oc] * s;
            }
            float* orow = out + (size_t)(bb * Cout + oc) * HW + rp0;
            #pragma unroll
            for (int nt = 0; nt < 4; nt++) {
                const int pc = wn * 32 + nt * 8 + 2 * tg;
                float v0 = acc[mt][nt][half * 2 + 0];
                float v1 = acc[mt][nt][half * 2 + 1];
                if (DO_BN) {
                    v0 = v0 * scale + bias;  v0 = (v0 >= 0.f) ? v0 : 0.1f * v0;
                    v1 = v1 * scale + bias;  v1 = (v1 >= 0.f) ? v1 : 0.1f * v1;
                }
                float2 vv; vv.x = v0; vv.y = v1;
                *reinterpret_cast<float2*>(&orow[pc]) = vv;
            }
        }
    }
}

// ---------------------------------------------------------------------------
// Fused: softmax over 9 logits per (b, group, ho, wo), then weighted unfold
// sum over the 3x3 stride-2 patch. Channel for (i, g) is ch = i*G + g.
// ---------------------------------------------------------------------------
__global__ void adaptive_ds_kernel(
    const float* __restrict__ x, const float* __restrict__ logits,
    float* __restrict__ out,
    int Cin, int G, int Hin, int Win, int Bsz)
{
    const int idx = blockIdx.x * blockDim.x + threadIdx.x;
    const int total = Bsz * G * HW_;
    if (idx >= total) return;

    const int wo = idx % WO_;
    int t = idx / WO_;
    const int ho = t % HO_;  t /= HO_;
    const int g  = t % G;
    const int b  = t / G;

    float lg[9];
    float mx = -1e30f;
    const size_t lbase = ((size_t)(b * G * 9 + g * 9) * HW_) + ho * WO_ + wo;
    #pragma unroll
    for (int k = 0; k < 9; k++) {
        lg[k] = logits[lbase + (size_t)k * HW_];
        mx = fmaxf(mx, lg[k]);
    }
    float s = 0.f;
    #pragma unroll
    for (int k = 0; k < 9; k++) { lg[k] = __expf(lg[k] - mx); s += lg[k]; }
    const float inv = 1.f / s;
    #pragma unroll
    for (int k = 0; k < 9; k++) lg[k] *= inv;

    const int cpg = Cin / G;
    for (int i = 0; i < cpg; i++) {
        const int ch = i * G + g;
        const float* xb = x + (size_t)(b * Cin + ch) * Hin * Win;
        float acc = 0.f;
        #pragma unroll
        for (int kh = 0; kh < 3; kh++) {
            const int hi = 2 * ho + kh - 1;
            if (hi < 0 || hi >= Hin) continue;
            #pragma unroll
            for (int kw = 0; kw < 3; kw++) {
                const int wi = 2 * wo + kw - 1;
                if (wi < 0 || wi >= Win) continue;
                acc += lg[kh * 3 + kw] * __ldg(&xb[(size_t)hi * Win + wi]);
            }
        }
        out[((size_t)(b * Cin + ch) * HW_) + ho * WO_ + wo] = acc;
    }
}

// ---------------------------------------------------------------------------
// Cost volumes. Output (2, 32, 24, 80, 144):
//   c in [0,8):   gwc corr  mean_{cc<12} l[g*12+cc][w] * r[g*12+cc][w-d]
//   c in [8,20):  l_c[c-8][w]       if w>=d else 0
//   c in [20,32): r_c[c-20][w-d]    if w>=d else 0
// ---------------------------------------------------------------------------
__global__ void build_volume_kernel(
    const float* __restrict__ g8x, const float* __restrict__ c8x,
    float* __restrict__ out)
{
    const int W = WO_, H = HO_, D = 24, OC = 32;
    const int total = 2 * OC * D * H * W;
    const int idx = blockIdx.x * blockDim.x + threadIdx.x;
    if (idx >= total) return;

    const int w = idx % W;
    int t = idx / W;
    const int h = t % H;  t /= H;
    const int d = t % D;  t /= D;
    const int c = t % OC;
    const int b = t / OC;

    float v = 0.f;
    if (c < 8) {
        if (w >= d) {
            const float* l = g8x + ((size_t)(b       * 96 + c * 12) * H + h) * W;
            const float* r = g8x + ((size_t)((b + 2) * 96 + c * 12) * H + h) * W;
            float acc = 0.f;
            #pragma unroll
            for (int cc = 0; cc < 12; cc++)
                acc += __ldg(&l[(size_t)cc * H * W + w]) * __ldg(&r[(size_t)cc * H * W + w - d]);
            v = acc * (1.f / 12.f);
        }
    } else if (c < 20) {
        const int ch = c - 8;
        if (w >= d) v = __ldg(&c8x[((size_t)(b * 12 + ch) * H + h) * W + w]);
    } else {
        const int ch = c - 20;
        if (w >= d) v = __ldg(&c8x[((size_t)((b + 2) * 12 + ch) * H + h) * W + w - d]);
    }
    out[idx] = v;
}

// ---------------------------------------------------------------------------
extern "C" void kernel_launch(void* const* d_in, const int* in_sizes, int n_in,
                              void* d_out, int out_size)
{
    const float* gwc = (const float*)d_in[0];
    const float* cat = (const float*)d_in[1];
    const float* gw1 = (const float*)d_in[2];
    const float* gbg = (const float*)d_in[3];
    const float* gbb = (const float*)d_in[4];
    const float* gbm = (const float*)d_in[5];
    const float* gbv = (const float*)d_in[6];
    const float* gw2 = (const float*)d_in[7];
    const float* cw1 = (const float*)d_in[8];
    const float* cbg = (const float*)d_in[9];
    const float* cbb = (const float*)d_in[10];
    const float* cbm = (const float*)d_in[11];
    const float* cbv = (const float*)d_in[12];
    const float* cw2 = (const float*)d_in[13];
    float* out = (float*)d_out;

    float *y1, *mask, *g8x, *cy1, *cmask, *c8x;
    cudaGetSymbolAddress((void**)&y1,    g_y1);
    cudaGetSymbolAddress((void**)&mask,  g_mask);
    cudaGetSymbolAddress((void**)&g8x,   g_g8x);
    cudaGetSymbolAddress((void**)&cy1,   g_cy1);
    cudaGetSymbolAddress((void**)&cmask, g_cmask);
    cudaGetSymbolAddress((void**)&c8x,   g_c8x);

    const int nTiles = (4 * HW_) / 128;   // 360 (exact)

    // gwc branch
    conv_mma_kernel<3, true><<<dim3(nTiles, 3), 256>>>(
        gwc, gw1, gbg, gbb, gbm, gbv, y1, 96, 192, 160, 288, HO_, WO_, 2, 1);
    conv_mma_kernel<1, false><<<dim3(nTiles, 3), 256>>>(
        y1, gw2, nullptr, nullptr, nullptr, nullptr, mask, 192, 144, HO_, WO_, HO_, WO_, 1, 0);
    adaptive_ds_kernel<<<(4 * 16 * HW_ + 255) / 256, 256>>>(
        gwc, mask, g8x, 96, 16, 160, 288, 4);

    // concat branch
    conv_mma_kernel<3, true><<<dim3(nTiles, 1), 256>>>(
        cat, cw1, cbg, cbb, cbm, cbv, cy1, 12, 24, 160, 288, HO_, WO_, 2, 1);
    conv_mma_kernel<1, false><<<dim3(nTiles, 2), 256>>>(
        cy1, cw2, nullptr, nullptr, nullptr, nullptr, cmask, 24, 108, HO_, WO_, HO_, WO_, 1, 0);
    adaptive_ds_kernel<<<(4 * 12 * HW_ + 255) / 256, 256>>>(
        cat, cmask, c8x, 12, 12, 160, 288, 4);

    // volumes -> d_out
    build_volume_kernel<<<(2 * 32 * 24 * HW_ + 255) / 256, 256>>>(g8x, c8x, out);
}